// round 1
// baseline (speedup 1.0000x reference)
#include <cuda_runtime.h>
#include <math.h>
#include <stdint.h>

// ---------------- problem constants ----------------
#define DM   1024      // d_model
#define NH   16        // heads
#define DQ   64        // d_qkv
#define DFF  4096      // d_ff
#define NL   6         // layers
#define SL   1024      // seq len
#define NB   8         // batch
#define NT   (NB*SL)   // tokens = 8192
#define NA   16        // actions
#define LN_EPS 1e-5f

// ---------------- scratch (static device memory; no allocations) ----------------
__device__ float g_h  [(size_t)NT*DM];
__device__ float g_res[(size_t)NT*DM];
__device__ float g_q  [(size_t)NT*DM];
__device__ float g_k  [(size_t)NT*DM];
__device__ float g_v  [(size_t)NT*DM];
__device__ float g_ctx[(size_t)NT*DM];
__device__ float g_ff [(size_t)NT*DFF];
__device__ float g_wq [(size_t)NL*DM*DM];
__device__ float g_wk [(size_t)NL*DM*DM];
__device__ float g_wv [(size_t)NL*DM*DM];
__device__ unsigned g_mbits[(size_t)NB*SL*SL/32];

// ---------------- embedding + positional encoding ----------------
// h[tok][d] = embed[x[tok]][d]*sqrt(DM) + pe(l, d)
__global__ __launch_bounds__(256) void embed_kernel(const int* __restrict__ x,
                                                    const float* __restrict__ embed)
{
    int tok = blockIdx.x;                 // 0..8191
    int l   = tok & (SL-1);
    int row = x[tok];
    const float* e = embed + (size_t)row * DM;
    float* out = g_h + (size_t)tok * DM;
    const float LOG2_10000 = 13.287712379549449f;
    for (int d = threadIdx.x; d < DM; d += 256) {
        float p = (float)(d & ~1) * (1.0f / (float)DM);       // 2*(d/2)/DM
        float inv_div = exp2f(-LOG2_10000 * p);               // 1/10000^p
        float ang = (float)(l + 1) * inv_div;
        float pe = (d & 1) ? cosf(ang) : sinf(ang);
        out[d] = e[d] * 32.0f + pe;                           // sqrt(1024)=32
    }
}

// ---------------- pack QKV weights [NL][NH][DM][DQ] -> [NL][DM][NH*DQ] ----------------
__global__ __launch_bounds__(256) void pack_qkv_kernel(const float* __restrict__ Wq,
                                                       const float* __restrict__ Wk,
                                                       const float* __restrict__ Wv)
{
    size_t t = (size_t)blockIdx.x * 256 + threadIdx.x;    // over NL*DM*DM
    if (t >= (size_t)NL*DM*DM) return;
    int n = (int)(t & (DM-1));
    size_t rem = t >> 10;
    int m = (int)(rem & (DM-1));
    int i = (int)(rem >> 10);
    int hh = n >> 6, dq = n & 63;
    size_t src = (((size_t)(i*NH + hh) * DM + m) * DQ + dq);
    g_wq[t] = Wq[src];
    g_wk[t] = Wk[src];
    g_wv[t] = Wv[src];
}

// ---------------- pack mask [B,L,L] int32 -> bitmask ----------------
__global__ __launch_bounds__(256) void pack_mask_kernel(const int* __restrict__ mask)
{
    size_t w = (size_t)blockIdx.x * 256 + threadIdx.x;    // over NB*SL*SL/32
    if (w >= (size_t)NB*SL*SL/32) return;
    const int* p = mask + w * 32;
    unsigned bits = 0;
    #pragma unroll
    for (int j = 0; j < 32; j++) bits |= (p[j] != 0 ? 1u : 0u) << j;
    g_mbits[w] = bits;
}

// ---------------- generic tiled fp32 GEMM ----------------
// C[M,N] = A[M,K] @ B[K,N] (+bias per col) (optional ReLU). M%128==0, N%128==0, K%16==0.
#define BM 128
#define BN 128
#define BKT 16
#define TM 8
#define TN 8

template<bool RELU>
__global__ __launch_bounds__(256) void gemm_kernel(const float* __restrict__ A,
                                                   const float* __restrict__ B,
                                                   const float* __restrict__ bias,
                                                   float* __restrict__ C,
                                                   int M, int N, int K)
{
    __shared__ float As[BKT][BM + 1];
    __shared__ float Bs[BKT][BN];
    int tid = threadIdx.x;
    int bm = blockIdx.y, bn = blockIdx.x;
    const float* Ab = A + (size_t)bm * BM * K;
    const float* Bb = B + (size_t)bn * BN;

    int tr = tid >> 4, tc = tid & 15;      // 16x16 thread grid, 8x8 microtile
    int arow = tid >> 2;                   // 0..63, rows arow & arow+64
    int acol = (tid & 3) * 4;              // 0,4,8,12
    int brow = tid >> 5;                   // 0..7, rows brow & brow+8
    int bcol = (tid & 31) * 4;

    float acc[TM][TN];
    #pragma unroll
    for (int i = 0; i < TM; i++)
        #pragma unroll
        for (int j = 0; j < TN; j++) acc[i][j] = 0.f;

    for (int k0 = 0; k0 < K; k0 += BKT) {
        float4 a0 = *(const float4*)(Ab + (size_t)arow      * K + k0 + acol);
        float4 a1 = *(const float4*)(Ab + (size_t)(arow+64) * K + k0 + acol);
        float4 b0 = *(const float4*)(Bb + (size_t)(k0+brow)   * N + bcol);
        float4 b1 = *(const float4*)(Bb + (size_t)(k0+brow+8) * N + bcol);
        __syncthreads();   // previous tile fully consumed
        As[acol+0][arow]    = a0.x; As[acol+1][arow]    = a0.y;
        As[acol+2][arow]    = a0.z; As[acol+3][arow]    = a0.w;
        As[acol+0][arow+64] = a1.x; As[acol+1][arow+64] = a1.y;
        As[acol+2][arow+64] = a1.z; As[acol+3][arow+64] = a1.w;
        *(float4*)&Bs[brow][bcol]   = b0;
        *(float4*)&Bs[brow+8][bcol] = b1;
        __syncthreads();
        #pragma unroll
        for (int k = 0; k < BKT; k++) {
            float ra[TM], rb[TN];
            #pragma unroll
            for (int i = 0; i < TM; i++) ra[i] = As[k][tr*TM + i];
            #pragma unroll
            for (int j = 0; j < TN; j++) rb[j] = Bs[k][tc*TN + j];
            #pragma unroll
            for (int i = 0; i < TM; i++)
                #pragma unroll
                for (int j = 0; j < TN; j++)
                    acc[i][j] = fmaf(ra[i], rb[j], acc[i][j]);
        }
    }

    float* Cb = C + (size_t)bm * BM * N + (size_t)bn * BN;
    const float* bp = bias ? (bias + (size_t)bn * BN) : nullptr;
    #pragma unroll
    for (int i = 0; i < TM; i++) {
        int row = tr*TM + i;
        #pragma unroll
        for (int j = 0; j < TN; j += 4) {
            int col = tc*TN + j;
            float4 v;
            v.x = acc[i][j+0]; v.y = acc[i][j+1];
            v.z = acc[i][j+2]; v.w = acc[i][j+3];
            if (bp) { v.x += bp[col+0]; v.y += bp[col+1]; v.z += bp[col+2]; v.w += bp[col+3]; }
            if (RELU) {
                v.x = fmaxf(v.x, 0.f); v.y = fmaxf(v.y, 0.f);
                v.z = fmaxf(v.z, 0.f); v.w = fmaxf(v.w, 0.f);
            }
            *(float4*)(Cb + (size_t)row * N + col) = v;
        }
    }
}

// ---------------- flash attention (fp32, thread-per-query-row) ----------------
// grid: (NB*NH, SL/128), block: 128. Online softmax, 16-key smem tiles.
__global__ __launch_bounds__(128) void flash_kernel()
{
    __shared__ float Ks[16*64];
    __shared__ float Vs[16*64];
    int bh = blockIdx.x;
    int b = bh >> 4, hh = bh & 15;
    int l = blockIdx.y * 128 + threadIdx.x;
    size_t tok = (size_t)b * SL + l;

    float q[64], o[64];
    const float* qp = g_q + tok * DM + hh * DQ;
    #pragma unroll
    for (int d = 0; d < 64; d++) { q[d] = qp[d]; o[d] = 0.f; }

    float mrun = -1e30f, ssum = 0.f;
    unsigned mrow = (unsigned)(b * SL + l) * 32u;   // word base for this mask row

    for (int t = 0; t < SL/16; t++) {
        __syncthreads();
        #pragma unroll
        for (int r = 0; r < 2; r++) {
            int q4 = threadIdx.x + r * 128;         // 0..255 float4 slots
            int kk = q4 >> 4, d4 = q4 & 15;
            size_t off = ((size_t)b * SL + t*16 + kk) * DM + hh * DQ + d4 * 4;
            ((float4*)Ks)[q4] = *(const float4*)(g_k + off);
            ((float4*)Vs)[q4] = *(const float4*)(g_v + off);
        }
        __syncthreads();

        unsigned bits = g_mbits[mrow + (t >> 1)] >> ((t & 1) * 16);
        float s[16];
        #pragma unroll
        for (int j = 0; j < 16; j++) {
            float a = 0.f;
            #pragma unroll
            for (int d = 0; d < 64; d++) a = fmaf(q[d], Ks[j*64 + d], a);
            a *= 0.125f;                            // 1/sqrt(64)
            if (!((bits >> j) & 1u)) a = -1e9f;
            s[j] = a;
        }
        float tmax = mrun;
        #pragma unroll
        for (int j = 0; j < 16; j++) tmax = fmaxf(tmax, s[j]);
        float alpha = __expf(mrun - tmax);
        mrun = tmax;
        ssum *= alpha;
        #pragma unroll
        for (int d = 0; d < 64; d++) o[d] *= alpha;
        #pragma unroll
        for (int j = 0; j < 16; j++) {
            float p = __expf(s[j] - mrun);
            ssum += p;
            #pragma unroll
            for (int d = 0; d < 64; d++) o[d] = fmaf(p, Vs[j*64 + d], o[d]);
        }
    }
    float inv = 1.0f / ssum;
    float* op = g_ctx + tok * DM + hh * DQ;
    #pragma unroll
    for (int d = 0; d < 64; d++) op[d] = o[d] * inv;
}

// ---------------- residual add + layernorm ----------------
// out = LN(x+y)*s + b ; block per token, 256 threads
__global__ __launch_bounds__(256) void add_ln_kernel(const float* x, const float* y,
                                                     const float* __restrict__ sc,
                                                     const float* __restrict__ bt,
                                                     float* out)
{
    int tok = blockIdx.x;
    const float* xp = x + (size_t)tok * DM;
    const float* yp = y + (size_t)tok * DM;
    float* op = out + (size_t)tok * DM;
    __shared__ float red[8];

    float v[4]; float sum = 0.f;
    #pragma unroll
    for (int i = 0; i < 4; i++) {
        int d = threadIdx.x + 256*i;
        v[i] = xp[d] + yp[d];
        sum += v[i];
    }
    #pragma unroll
    for (int off = 16; off > 0; off >>= 1) sum += __shfl_xor_sync(0xffffffffu, sum, off);
    if ((threadIdx.x & 31) == 0) red[threadIdx.x >> 5] = sum;
    __syncthreads();
    float tot = 0.f;
    #pragma unroll
    for (int i = 0; i < 8; i++) tot += red[i];
    float mu = tot * (1.0f / (float)DM);

    float var = 0.f;
    #pragma unroll
    for (int i = 0; i < 4; i++) { float dlt = v[i] - mu; var = fmaf(dlt, dlt, var); }
    __syncthreads();
    #pragma unroll
    for (int off = 16; off > 0; off >>= 1) var += __shfl_xor_sync(0xffffffffu, var, off);
    if ((threadIdx.x & 31) == 0) red[threadIdx.x >> 5] = var;
    __syncthreads();
    float vtot = 0.f;
    #pragma unroll
    for (int i = 0; i < 8; i++) vtot += red[i];
    float inv = rsqrtf(vtot * (1.0f / (float)DM) + LN_EPS);

    #pragma unroll
    for (int i = 0; i < 4; i++) {
        int d = threadIdx.x + 256*i;
        op[d] = (v[i] - mu) * inv * sc[d] + bt[d];
    }
}

// ---------------- output head: logits of last token + log_softmax ----------------
// grid: NB blocks, 512 threads (16 warps -> one action each)
__global__ __launch_bounds__(512) void out_kernel(const float* __restrict__ w,
                                                  const float* __restrict__ bias,
                                                  float* __restrict__ out)
{
    int b = blockIdx.x;
    const float* hp = g_h + ((size_t)(b * SL + SL - 1)) * DM;
    __shared__ float logits[NA];
    int wp = threadIdx.x >> 5, lane = threadIdx.x & 31;
    float s = 0.f;
    for (int d = lane; d < DM; d += 32) s = fmaf(hp[d], w[d * NA + wp], s);
    #pragma unroll
    for (int off = 16; off > 0; off >>= 1) s += __shfl_xor_sync(0xffffffffu, s, off);
    if (lane == 0) logits[wp] = s + bias[wp];
    __syncthreads();
    if (threadIdx.x == 0) {
        float mx = -1e30f;
        for (int a = 0; a < NA; a++) mx = fmaxf(mx, logits[a]);
        float se = 0.f;
        for (int a = 0; a < NA; a++) se += expf(logits[a] - mx);
        float lse = mx + logf(se);
        for (int a = 0; a < NA; a++) out[b * NA + a] = logits[a] - lse;
    }
}

// ---------------- host launch ----------------
static float* symaddr(const void* s) { void* p = nullptr; cudaGetSymbolAddress(&p, s); return (float*)p; }

extern "C" void kernel_launch(void* const* d_in, const int* in_sizes, int n_in,
                              void* d_out, int out_size)
{
    (void)in_sizes; (void)n_in; (void)out_size;
    const int*   x     = (const int*)d_in[0];
    const int*   mask  = (const int*)d_in[1];
    const float* embed = (const float*)d_in[2];
    const float* Wq    = (const float*)d_in[3];
    const float* Wk    = (const float*)d_in[4];
    const float* Wv    = (const float*)d_in[5];
    const float* Wo_w  = (const float*)d_in[6];
    const float* Wo_b  = (const float*)d_in[7];
    const float* ln1_s = (const float*)d_in[8];
    const float* ln1_b = (const float*)d_in[9];
    const float* ff_w1 = (const float*)d_in[10];
    const float* ff_b1 = (const float*)d_in[11];
    const float* ff_w2 = (const float*)d_in[12];
    const float* ff_b2 = (const float*)d_in[13];
    const float* ln2_s = (const float*)d_in[14];
    const float* ln2_b = (const float*)d_in[15];
    const float* out_w = (const float*)d_in[16];
    const float* out_b = (const float*)d_in[17];
    float* out = (float*)d_out;

    float* h_p   = symaddr(g_h);
    float* res_p = symaddr(g_res);
    float* q_p   = symaddr(g_q);
    float* k_p   = symaddr(g_k);
    float* v_p   = symaddr(g_v);
    float* ctx_p = symaddr(g_ctx);
    float* ff_p  = symaddr(g_ff);
    float* wq_p  = symaddr(g_wq);
    float* wk_p  = symaddr(g_wk);
    float* wv_p  = symaddr(g_wv);

    embed_kernel<<<NT, 256>>>(x, embed);
    pack_qkv_kernel<<<(NL*DM*DM + 255)/256, 256>>>(Wq, Wk, Wv);
    pack_mask_kernel<<<((size_t)NB*SL*SL/32 + 255)/256, 256>>>(mask);

    dim3 gD(DM/BN, NT/BM);    // N=1024 GEMMs
    dim3 gF(DFF/BN, NT/BM);   // N=4096 GEMM

    for (int i = 0; i < NL; i++) {
        size_t wOff  = (size_t)i * DM * DM;
        gemm_kernel<false><<<gD, 256>>>(h_p, wq_p + wOff, nullptr, q_p, NT, DM, DM);
        gemm_kernel<false><<<gD, 256>>>(h_p, wk_p + wOff, nullptr, k_p, NT, DM, DM);
        gemm_kernel<false><<<gD, 256>>>(h_p, wv_p + wOff, nullptr, v_p, NT, DM, DM);
        flash_kernel<<<dim3(NB*NH, SL/128), 128>>>();
        gemm_kernel<false><<<gD, 256>>>(ctx_p, Wo_w + wOff, Wo_b + (size_t)i*DM, res_p, NT, DM, DM);
        add_ln_kernel<<<NT, 256>>>(h_p, res_p, ln1_s + (size_t)i*DM, ln1_b + (size_t)i*DM, h_p);
        gemm_kernel<true ><<<gF, 256>>>(h_p, ff_w1 + (size_t)i*DM*DFF, ff_b1 + (size_t)i*DFF, ff_p, NT, DFF, DM);
        gemm_kernel<false><<<gD, 256>>>(ff_p, ff_w2 + (size_t)i*DFF*DM, ff_b2 + (size_t)i*DM, res_p, NT, DM, DFF);
        add_ln_kernel<<<NT, 256>>>(h_p, res_p, ln2_s + (size_t)i*DM, ln2_b + (size_t)i*DM, h_p);
    }
    out_kernel<<<NB, 512>>>(out_w, out_b, out);
}

// round 4
// speedup vs baseline: 3.0821x; 3.0821x over previous
#include <cuda_runtime.h>
#include <cuda_fp16.h>
#include <math.h>
#include <stdint.h>

// ---------------- problem constants ----------------
#define DM   1024
#define NH   16
#define DQ   64
#define DFF  4096
#define NL   6
#define SL   1024
#define NB   8
#define NT   (NB*SL)
#define NA   16
#define LN_EPS 1e-5f
#define DQKV 3072

// ---------------- scratch (static device memory) ----------------
__device__ float  g_h   [(size_t)NT*DM];
__device__ float  g_res [(size_t)NT*DM];
__device__ float  g_qkv [(size_t)NT*DQKV];
__device__ __half g_h16 [(size_t)NT*DM];
__device__ __half g_ctx16[(size_t)NT*DM];
__device__ __half g_ff16[(size_t)NT*DFF];
__device__ __half g_wqkv16[(size_t)NL*DQKV*DM];   // [L][3072][1024] n-major, k contiguous
__device__ __half g_wo16 [(size_t)NL*DM*DM];
__device__ __half g_w116 [(size_t)NL*DM*DFF];
__device__ __half g_w216 [(size_t)NL*DFF*DM];
__device__ unsigned g_mbits[(size_t)NB*SL*SL/32];

// ================= PTX helpers (sm_80-compatible subset) =================
__device__ __forceinline__ uint32_t smem_u32(const void* p) {
    uint32_t a;
    asm("{ .reg .u64 t; cvta.to.shared.u64 t, %1; cvt.u32.u64 %0, t; }" : "=r"(a) : "l"(p));
    return a;
}
#define CP_ASYNC16(dst, src) \
    asm volatile("cp.async.cg.shared.global [%0], [%1], 16;" :: "r"(dst), "l"(src) : "memory")
#define CP_COMMIT() asm volatile("cp.async.commit_group;" ::: "memory")
#define CP_WAIT2()  asm volatile("cp.async.wait_group 2;" ::: "memory")

__device__ __forceinline__ void ldsm4(uint32_t& r0, uint32_t& r1, uint32_t& r2, uint32_t& r3,
                                      uint32_t addr) {
    asm volatile("ldmatrix.sync.aligned.m8n8.x4.shared.b16 {%0,%1,%2,%3}, [%4];"
                 : "=r"(r0), "=r"(r1), "=r"(r2), "=r"(r3) : "r"(addr));
}
__device__ __forceinline__ void mma16816(float* c, const uint32_t* a, const uint32_t* b) {
    asm volatile("mma.sync.aligned.m16n8k16.row.col.f32.f16.f16.f32 "
                 "{%0,%1,%2,%3}, {%4,%5,%6,%7}, {%8,%9}, {%0,%1,%2,%3};"
                 : "+f"(c[0]), "+f"(c[1]), "+f"(c[2]), "+f"(c[3])
                 : "r"(a[0]), "r"(a[1]), "r"(a[2]), "r"(a[3]), "r"(b[0]), "r"(b[1]));
}

// ================= HMMA fp16 GEMM =================
// C[M,N] = A16[M,K] @ B16[N,K]^T.  Tile 128x128, BK=32, 4-stage cp.async pipeline.
// grid = (N/128, M/128), block = 256 (8 warps: 4 m x 2 n), each warp 32x64.
#define BKH   32                    // k per stage (halfs)
#define RSB   80                    // smem row stride bytes (64 data + 16 pad)
#define ASZ   (128*RSB)             // 10240 B per stage per operand
#define NSTG  4
#define GSMEM (2*NSTG*ASZ)          // 81920 B

template<bool FF1>
__global__ void __launch_bounds__(256, 2)
gemm16_kernel(const __half* __restrict__ A, const __half* __restrict__ B,
              const float* __restrict__ bias, float* __restrict__ C,
              __half* __restrict__ C16, int N, int K)
{
    extern __shared__ char smem[];
    uint32_t sA = smem_u32(smem);               // NSTG A stages
    uint32_t sB = sA + NSTG*ASZ;                // NSTG B stages
    int tid = threadIdx.x, wid = tid >> 5, lane = tid & 31;
    int wm = wid & 3, wn = wid >> 2;            // warp tile: m 32, n 64

    const __half* Ab = A + (size_t)blockIdx.y * 128 * K;
    const __half* Bb = B + (size_t)blockIdx.x * 128 * K;
    int KT = K / BKH;

    // async load of one stage (A and B, 2 chunks each per thread)
    auto load_stage = [&](int kt) {
        int s = kt & (NSTG-1);
        #pragma unroll
        for (int j = 0; j < 2; j++) {
            int idx = tid + j * 256;            // 0..511
            int row = idx >> 2, ch = idx & 3;
            const void* srcA = Ab + (size_t)row * K + kt * BKH + ch * 8;
            const void* srcB = Bb + (size_t)row * K + kt * BKH + ch * 8;
            CP_ASYNC16(sA + s*ASZ + row*RSB + ch*16, srcA);
            CP_ASYNC16(sB + s*ASZ + row*RSB + ch*16, srcB);
        }
    };

    // prologue
    #pragma unroll
    for (int kt = 0; kt < NSTG-1; kt++) { load_stage(kt); CP_COMMIT(); }

    float acc[2][8][4];
    #pragma unroll
    for (int mt = 0; mt < 2; mt++)
        #pragma unroll
        for (int nt = 0; nt < 8; nt++)
            #pragma unroll
            for (int r = 0; r < 4; r++) acc[mt][nt][r] = 0.f;

    // ldmatrix lane addressing (row within 128-row tile, 16B chunk along k)
    int a_lm = lane & 15, a_kc = lane >> 4;            // A: rows m..m+15, k chunk 0/1
    int b_nr = (lane & 7) + ((lane >> 4) << 3);        // B: n row
    int b_kc = (lane >> 3) & 1;

    for (int kt = 0; kt < KT; kt++) {
        int s = kt & (NSTG-1);
        CP_WAIT2();
        __syncthreads();
        int ktn = kt + NSTG - 1;
        if (ktn < KT) load_stage(ktn);
        CP_COMMIT();                                    // empty group ok at tail

        uint32_t aS = sA + s*ASZ, bS = sB + s*ASZ;
        #pragma unroll
        for (int ks = 0; ks < 2; ks++) {
            int kb = ks * 32 + a_kc * 16;               // byte offset along k
            uint32_t afr[2][4];
            #pragma unroll
            for (int mt = 0; mt < 2; mt++) {
                uint32_t ad = aS + (wm*32 + mt*16 + a_lm) * RSB + kb;
                ldsm4(afr[mt][0], afr[mt][1], afr[mt][2], afr[mt][3], ad);
            }
            uint32_t bfr[8][2];
            #pragma unroll
            for (int p = 0; p < 4; p++) {
                uint32_t r0, r1, r2, r3;
                uint32_t bd = bS + (wn*64 + p*16 + b_nr) * RSB + ks*32 + b_kc*16;
                ldsm4(r0, r1, r2, r3, bd);
                bfr[2*p][0] = r0; bfr[2*p][1] = r1;
                bfr[2*p+1][0] = r2; bfr[2*p+1][1] = r3;
            }
            #pragma unroll
            for (int mt = 0; mt < 2; mt++)
                #pragma unroll
                for (int nt = 0; nt < 8; nt++)
                    mma16816(acc[mt][nt], afr[mt], bfr[nt]);
        }
        __syncthreads();
    }

    // epilogue
    int mbase = blockIdx.y * 128 + wm * 32;
    int nbase = blockIdx.x * 128 + wn * 64;
    int lrow = lane >> 2, lcol = (lane & 3) * 2;
    #pragma unroll
    for (int mt = 0; mt < 2; mt++) {
        #pragma unroll
        for (int nt = 0; nt < 8; nt++) {
            int row = mbase + mt*16 + lrow;
            int col = nbase + nt*8 + lcol;
            float c0 = acc[mt][nt][0], c1 = acc[mt][nt][1];
            float c2 = acc[mt][nt][2], c3 = acc[mt][nt][3];
            if (FF1) {
                float b0 = bias[col], b1 = bias[col+1];
                __half2 h0 = __floats2half2_rn(fmaxf(c0+b0, 0.f), fmaxf(c1+b1, 0.f));
                __half2 h1 = __floats2half2_rn(fmaxf(c2+b0, 0.f), fmaxf(c3+b1, 0.f));
                *(__half2*)(C16 + (size_t)row * N + col)       = h0;
                *(__half2*)(C16 + (size_t)(row+8) * N + col)   = h1;
            } else {
                if (bias) { float b0 = bias[col], b1 = bias[col+1];
                            c0 += b0; c1 += b1; c2 += b0; c3 += b1; }
                *(float2*)(C + (size_t)row * N + col)     = make_float2(c0, c1);
                *(float2*)(C + (size_t)(row+8) * N + col) = make_float2(c2, c3);
            }
        }
    }
}

// ================= weight transpose + fp16 convert =================
__global__ __launch_bounds__(256) void transconv_kernel(const float* __restrict__ src,
                                                        __half* __restrict__ dst,
                                                        int K, int N,
                                                        size_t dO, int nInner, size_t dI)
{
    __shared__ float t[32][33];
    int z = blockIdx.z;
    src += (size_t)z * K * N;
    dst += (size_t)(z / nInner) * dO + (size_t)(z % nInner) * dI;
    int k0 = blockIdx.y * 32, n0 = blockIdx.x * 32;
    int c = threadIdx.x & 31, r0 = threadIdx.x >> 5;
    #pragma unroll
    for (int rr = 0; rr < 32; rr += 8)
        t[r0 + rr][c] = src[(size_t)(k0 + r0 + rr) * N + n0 + c];
    __syncthreads();
    #pragma unroll
    for (int rr = 0; rr < 32; rr += 8)
        dst[(size_t)(n0 + r0 + rr) * K + k0 + c] = __float2half(t[c][r0 + rr]);
}

// ================= embedding + positional encoding =================
__global__ __launch_bounds__(256) void embed_kernel(const int* __restrict__ x,
                                                    const float* __restrict__ embed)
{
    int tok = blockIdx.x;
    int l   = tok & (SL-1);
    const float* e = embed + (size_t)x[tok] * DM;
    float*  out   = g_h   + (size_t)tok * DM;
    __half* out16 = g_h16 + (size_t)tok * DM;
    const float LOG2_10000 = 13.287712379549449f;
    for (int d = threadIdx.x; d < DM; d += 256) {
        float p = (float)(d & ~1) * (1.0f / (float)DM);
        float inv_div = exp2f(-LOG2_10000 * p);
        float ang = (float)(l + 1) * inv_div;
        float pe = (d & 1) ? cosf(ang) : sinf(ang);
        float v = e[d] * 32.0f + pe;
        out[d] = v;
        out16[d] = __float2half(v);
    }
}

// ================= mask -> bitmask =================
__global__ __launch_bounds__(256) void pack_mask_kernel(const int* __restrict__ mask)
{
    size_t w = (size_t)blockIdx.x * 256 + threadIdx.x;
    if (w >= (size_t)NB*SL*SL/32) return;
    const int* p = mask + w * 32;
    unsigned bits = 0;
    #pragma unroll
    for (int j = 0; j < 32; j++) bits |= (p[j] != 0 ? 1u : 0u) << j;
    g_mbits[w] = bits;
}

// ================= flash attention (fp32) =================
__global__ __launch_bounds__(128) void flash_kernel()
{
    __shared__ float Ks[16*64];
    __shared__ float Vs[16*64];
    int bh = blockIdx.x;
    int b = bh >> 4, hh = bh & 15;
    int l = blockIdx.y * 128 + threadIdx.x;
    size_t tok = (size_t)b * SL + l;

    float q[64], o[64];
    const float4* qp = (const float4*)(g_qkv + tok * DQKV + hh * DQ);
    #pragma unroll
    for (int d4 = 0; d4 < 16; d4++) {
        float4 qv = qp[d4];
        q[4*d4+0]=qv.x; q[4*d4+1]=qv.y; q[4*d4+2]=qv.z; q[4*d4+3]=qv.w;
    }
    #pragma unroll
    for (int d = 0; d < 64; d++) o[d] = 0.f;

    float mrun = -1e30f, ssum = 0.f;
    unsigned mrow = (unsigned)(b * SL + l) * 32u;
    const float4* K4 = (const float4*)Ks;
    const float4* V4 = (const float4*)Vs;

    for (int t = 0; t < SL/16; t++) {
        __syncthreads();
        #pragma unroll
        for (int r = 0; r < 2; r++) {
            int q4 = threadIdx.x + r * 128;
            int kk = q4 >> 4, d4 = q4 & 15;
            size_t base = ((size_t)b * SL + t*16 + kk) * DQKV + hh * DQ + d4 * 4;
            ((float4*)Ks)[q4] = *(const float4*)(g_qkv + base + 1024);
            ((float4*)Vs)[q4] = *(const float4*)(g_qkv + base + 2048);
        }
        __syncthreads();

        unsigned bits = g_mbits[mrow + (t >> 1)] >> ((t & 1) * 16);
        float s[16];
        #pragma unroll
        for (int j = 0; j < 16; j++) {
            float a = 0.f;
            #pragma unroll
            for (int d4 = 0; d4 < 16; d4++) {
                float4 kv = K4[j*16 + d4];
                a = fmaf(q[4*d4+0], kv.x, a); a = fmaf(q[4*d4+1], kv.y, a);
                a = fmaf(q[4*d4+2], kv.z, a); a = fmaf(q[4*d4+3], kv.w, a);
            }
            a *= 0.125f;
            if (!((bits >> j) & 1u)) a = -1e9f;
            s[j] = a;
        }
        float tmax = mrun;
        #pragma unroll
        for (int j = 0; j < 16; j++) tmax = fmaxf(tmax, s[j]);
        float alpha = __expf(mrun - tmax);
        mrun = tmax;
        ssum *= alpha;
        #pragma unroll
        for (int d = 0; d < 64; d++) o[d] *= alpha;
        #pragma unroll
        for (int j = 0; j < 16; j++) {
            float p = __expf(s[j] - mrun);
            ssum += p;
            #pragma unroll
            for (int d4 = 0; d4 < 16; d4++) {
                float4 vv = V4[j*16 + d4];
                o[4*d4+0] = fmaf(p, vv.x, o[4*d4+0]);
                o[4*d4+1] = fmaf(p, vv.y, o[4*d4+1]);
                o[4*d4+2] = fmaf(p, vv.z, o[4*d4+2]);
                o[4*d4+3] = fmaf(p, vv.w, o[4*d4+3]);
            }
        }
    }
    float inv = 1.0f / ssum;
    __half* op = g_ctx16 + tok * DM + hh * DQ;
    #pragma unroll
    for (int d = 0; d < 64; d += 2) {
        __half2 h2 = __floats2half2_rn(o[d]*inv, o[d+1]*inv);
        *(__half2*)(op + d) = h2;
    }
}

// ================= residual add + layernorm =================
__global__ __launch_bounds__(256) void add_ln_kernel(const float* x, const float* y,
                                                     const float* __restrict__ sc,
                                                     const float* __restrict__ bt,
                                                     float* out, __half* out16)
{
    int tok = blockIdx.x;
    const float* xp = x + (size_t)tok * DM;
    const float* yp = y + (size_t)tok * DM;
    float*  op   = out   + (size_t)tok * DM;
    __half* op16 = out16 + (size_t)tok * DM;
    __shared__ float red[8];

    float v[4]; float sum = 0.f;
    #pragma unroll
    for (int i = 0; i < 4; i++) {
        int d = threadIdx.x + 256*i;
        v[i] = xp[d] + yp[d];
        sum += v[i];
    }
    #pragma unroll
    for (int off = 16; off > 0; off >>= 1) sum += __shfl_xor_sync(0xffffffffu, sum, off);
    if ((threadIdx.x & 31) == 0) red[threadIdx.x >> 5] = sum;
    __syncthreads();
    float tot = 0.f;
    #pragma unroll
    for (int i = 0; i < 8; i++) tot += red[i];
    float mu = tot * (1.0f / (float)DM);

    float var = 0.f;
    #pragma unroll
    for (int i = 0; i < 4; i++) { float dl = v[i] - mu; var = fmaf(dl, dl, var); }
    __syncthreads();
    #pragma unroll
    for (int off = 16; off > 0; off >>= 1) var += __shfl_xor_sync(0xffffffffu, var, off);
    if ((threadIdx.x & 31) == 0) red[threadIdx.x >> 5] = var;
    __syncthreads();
    float vtot = 0.f;
    #pragma unroll
    for (int i = 0; i < 8; i++) vtot += red[i];
    float inv = rsqrtf(vtot * (1.0f / (float)DM) + LN_EPS);

    #pragma unroll
    for (int i = 0; i < 4; i++) {
        int d = threadIdx.x + 256*i;
        float r = (v[i] - mu) * inv * sc[d] + bt[d];
        op[d] = r;
        op16[d] = __float2half(r);
    }
}

// ================= output head =================
__global__ __launch_bounds__(512) void out_kernel(const float* __restrict__ w,
                                                  const float* __restrict__ bias,
                                                  float* __restrict__ out)
{
    int b = blockIdx.x;
    const float* hp = g_h + ((size_t)(b * SL + SL - 1)) * DM;
    __shared__ float logits[NA];
    int wp = threadIdx.x >> 5, lane = threadIdx.x & 31;
    float s = 0.f;
    for (int d = lane; d < DM; d += 32) s = fmaf(hp[d], w[d * NA + wp], s);
    #pragma unroll
    for (int off = 16; off > 0; off >>= 1) s += __shfl_xor_sync(0xffffffffu, s, off);
    if (lane == 0) logits[wp] = s + bias[wp];
    __syncthreads();
    if (threadIdx.x == 0) {
        float mx = -1e30f;
        for (int a = 0; a < NA; a++) mx = fmaxf(mx, logits[a]);
        float se = 0.f;
        for (int a = 0; a < NA; a++) se += expf(logits[a] - mx);
        float lse = mx + logf(se);
        for (int a = 0; a < NA; a++) out[b * NA + a] = logits[a] - lse;
    }
}

// ================= host launch =================
template<typename T> static T* symaddr(const void* s) { void* p = nullptr; cudaGetSymbolAddress(&p, s); return (T*)p; }

extern "C" void kernel_launch(void* const* d_in, const int* in_sizes, int n_in,
                              void* d_out, int out_size)
{
    (void)in_sizes; (void)n_in; (void)out_size;
    const int*   x     = (const int*)d_in[0];
    const int*   mask  = (const int*)d_in[1];
    const float* embed = (const float*)d_in[2];
    const float* Wq    = (const float*)d_in[3];
    const float* Wk    = (const float*)d_in[4];
    const float* Wv    = (const float*)d_in[5];
    const float* Wo_w  = (const float*)d_in[6];
    const float* Wo_b  = (const float*)d_in[7];
    const float* ln1_s = (const float*)d_in[8];
    const float* ln1_b = (const float*)d_in[9];
    const float* ff_w1 = (const float*)d_in[10];
    const float* ff_b1 = (const float*)d_in[11];
    const float* ff_w2 = (const float*)d_in[12];
    const float* ff_b2 = (const float*)d_in[13];
    const float* ln2_s = (const float*)d_in[14];
    const float* ln2_b = (const float*)d_in[15];
    const float* out_w = (const float*)d_in[16];
    const float* out_b = (const float*)d_in[17];
    float* out = (float*)d_out;

    float*  h_p    = symaddr<float>(g_h);
    float*  res_p  = symaddr<float>(g_res);
    float*  qkv_p  = symaddr<float>(g_qkv);
    __half* h16_p  = symaddr<__half>(g_h16);
    __half* ctx16_p= symaddr<__half>(g_ctx16);
    __half* ff16_p = symaddr<__half>(g_ff16);
    __half* wqkv_p = symaddr<__half>(g_wqkv16);
    __half* wo_p   = symaddr<__half>(g_wo16);
    __half* w1_p   = symaddr<__half>(g_w116);
    __half* w2_p   = symaddr<__half>(g_w216);

    cudaFuncSetAttribute(gemm16_kernel<false>, cudaFuncAttributeMaxDynamicSharedMemorySize, GSMEM);
    cudaFuncSetAttribute(gemm16_kernel<true>,  cudaFuncAttributeMaxDynamicSharedMemorySize, GSMEM);

    embed_kernel<<<NT, 256>>>(x, embed);
    pack_mask_kernel<<<((size_t)NB*SL*SL/32 + 255)/256, 256>>>(mask);

    transconv_kernel<<<dim3(2, 32, NL*NH), 256>>>(Wq, wqkv_p,                   DM, DQ, (size_t)DQKV*DM, NH, (size_t)DQ*DM);
    transconv_kernel<<<dim3(2, 32, NL*NH), 256>>>(Wk, wqkv_p + (size_t)DM*DM,   DM, DQ, (size_t)DQKV*DM, NH, (size_t)DQ*DM);
    transconv_kernel<<<dim3(2, 32, NL*NH), 256>>>(Wv, wqkv_p + (size_t)2*DM*DM, DM, DQ, (size_t)DQKV*DM, NH, (size_t)DQ*DM);
    transconv_kernel<<<dim3(32, 32, NL), 256>>>(Wo_w,  wo_p, DM, DM,  (size_t)DM*DM,  1, 0);
    transconv_kernel<<<dim3(128, 32, NL), 256>>>(ff_w1, w1_p, DM, DFF, (size_t)DM*DFF, 1, 0);
    transconv_kernel<<<dim3(32, 128, NL), 256>>>(ff_w2, w2_p, DFF, DM, (size_t)DFF*DM, 1, 0);

    dim3 gQKV(DQKV/128, NT/128);
    dim3 gD(DM/128, NT/128);
    dim3 gF(DFF/128, NT/128);

    for (int i = 0; i < NL; i++) {
        gemm16_kernel<false><<<gQKV, 256, GSMEM>>>(h16_p, wqkv_p + (size_t)i*DQKV*DM, nullptr, qkv_p, nullptr, DQKV, DM);
        flash_kernel<<<dim3(NB*NH, SL/128), 128>>>();
        gemm16_kernel<false><<<gD, 256, GSMEM>>>(ctx16_p, wo_p + (size_t)i*DM*DM, Wo_b + (size_t)i*DM, res_p, nullptr, DM, DM);
        add_ln_kernel<<<NT, 256>>>(h_p, res_p, ln1_s + (size_t)i*DM, ln1_b + (size_t)i*DM, h_p, h16_p);
        gemm16_kernel<true><<<gF, 256, GSMEM>>>(h16_p, w1_p + (size_t)i*DM*DFF, ff_b1 + (size_t)i*DFF, nullptr, ff16_p, DFF, DM);
        gemm16_kernel<false><<<gD, 256, GSMEM>>>(ff16_p, w2_p + (size_t)i*DFF*DM, ff_b2 + (size_t)i*DM, res_p, nullptr, DM, DFF);
        add_ln_kernel<<<NT, 256>>>(h_p, res_p, ln2_s + (size_t)i*DM, ln2_b + (size_t)i*DM, h_p, h16_p);
    }
    out_kernel<<<NB, 512>>>(out_w, out_b, out);
}

// round 6
// speedup vs baseline: 7.7006x; 2.4985x over previous
#include <cuda_runtime.h>
#include <cuda_fp16.h>
#include <math.h>
#include <stdint.h>

// ---------------- problem constants ----------------
#define DM   1024
#define NH   16
#define DQ   64
#define DFF  4096
#define NL   6
#define SL   1024
#define NB   8
#define NT   (NB*SL)
#define NA   16
#define LN_EPS 1e-5f
#define DQKV 3072

// ---------------- scratch (static device memory) ----------------
__device__ float  g_h   [(size_t)NT*DM];
__device__ float  g_res [(size_t)NT*DM];
__device__ __half g_qkv16[(size_t)NT*DQKV];       // [tok][q|k|v each 16 heads x 64]
__device__ __half g_h16 [(size_t)NT*DM];
__device__ __half g_ctx16[(size_t)NT*DM];
__device__ __half g_ff16[(size_t)NT*DFF];
__device__ __half g_wqkv16[(size_t)NL*DQKV*DM];   // [L][3072][1024] n-major, k contiguous
__device__ __half g_wo16 [(size_t)NL*DM*DM];
__device__ __half g_w116 [(size_t)NL*DM*DFF];
__device__ __half g_w216 [(size_t)NL*DFF*DM];
__device__ unsigned g_mbits[(size_t)NB*SL*SL/32];

// ================= PTX helpers (sm_80-compatible subset) =================
__device__ __forceinline__ uint32_t smem_u32(const void* p) {
    uint32_t a;
    asm("{ .reg .u64 t; cvta.to.shared.u64 t, %1; cvt.u32.u64 %0, t; }" : "=r"(a) : "l"(p));
    return a;
}
#define CP_ASYNC16(dst, src) \
    asm volatile("cp.async.cg.shared.global [%0], [%1], 16;" :: "r"(dst), "l"(src) : "memory")
#define CP_COMMIT() asm volatile("cp.async.commit_group;" ::: "memory")
#define CP_WAIT2()  asm volatile("cp.async.wait_group 2;" ::: "memory")
#define CP_WAIT1()  asm volatile("cp.async.wait_group 1;" ::: "memory")

__device__ __forceinline__ void ldsm4(uint32_t& r0, uint32_t& r1, uint32_t& r2, uint32_t& r3,
                                      uint32_t addr) {
    asm volatile("ldmatrix.sync.aligned.m8n8.x4.shared.b16 {%0,%1,%2,%3}, [%4];"
                 : "=r"(r0), "=r"(r1), "=r"(r2), "=r"(r3) : "r"(addr));
}
__device__ __forceinline__ void ldsm4t(uint32_t& r0, uint32_t& r1, uint32_t& r2, uint32_t& r3,
                                       uint32_t addr) {
    asm volatile("ldmatrix.sync.aligned.m8n8.x4.trans.shared.b16 {%0,%1,%2,%3}, [%4];"
                 : "=r"(r0), "=r"(r1), "=r"(r2), "=r"(r3) : "r"(addr));
}
__device__ __forceinline__ void mma16816(float* c, const uint32_t* a, const uint32_t* b) {
    asm volatile("mma.sync.aligned.m16n8k16.row.col.f32.f16.f16.f32 "
                 "{%0,%1,%2,%3}, {%4,%5,%6,%7}, {%8,%9}, {%0,%1,%2,%3};"
                 : "+f"(c[0]), "+f"(c[1]), "+f"(c[2]), "+f"(c[3])
                 : "r"(a[0]), "r"(a[1]), "r"(a[2]), "r"(a[3]), "r"(b[0]), "r"(b[1]));
}

// ================= HMMA fp16 GEMM =================
// C[M,N] = A16[M,K] @ B16[N,K]^T.  Tile 128x128, BK=32, 4-stage cp.async pipeline.
// MODE: 0 = f32 out (+bias if non-null), 1 = f16 relu+bias, 2 = f16 plain.
#define BKH   32
#define RSB   80
#define ASZ   (128*RSB)
#define NSTG  4
#define GSMEM (2*NSTG*ASZ)

template<int MODE>
__global__ void __launch_bounds__(256, 2)
gemm16_kernel(const __half* __restrict__ A, const __half* __restrict__ B,
              const float* __restrict__ bias, float* __restrict__ C,
              __half* __restrict__ C16, int N, int K)
{
    extern __shared__ char smem[];
    uint32_t sA = smem_u32(smem);
    uint32_t sB = sA + NSTG*ASZ;
    int tid = threadIdx.x, wid = tid >> 5, lane = tid & 31;
    int wm = wid & 3, wn = wid >> 2;

    const __half* Ab = A + (size_t)blockIdx.y * 128 * K;
    const __half* Bb = B + (size_t)blockIdx.x * 128 * K;
    int KT = K / BKH;

    auto load_stage = [&](int kt) {
        int s = kt & (NSTG-1);
        #pragma unroll
        for (int j = 0; j < 2; j++) {
            int idx = tid + j * 256;
            int row = idx >> 2, ch = idx & 3;
            const void* srcA = Ab + (size_t)row * K + kt * BKH + ch * 8;
            const void* srcB = Bb + (size_t)row * K + kt * BKH + ch * 8;
            CP_ASYNC16(sA + s*ASZ + row*RSB + ch*16, srcA);
            CP_ASYNC16(sB + s*ASZ + row*RSB + ch*16, srcB);
        }
    };

    #pragma unroll
    for (int kt = 0; kt < NSTG-1; kt++) { load_stage(kt); CP_COMMIT(); }

    float acc[2][8][4];
    #pragma unroll
    for (int mt = 0; mt < 2; mt++)
        #pragma unroll
        for (int nt = 0; nt < 8; nt++)
            #pragma unroll
            for (int r = 0; r < 4; r++) acc[mt][nt][r] = 0.f;

    int a_lm = lane & 15, a_kc = lane >> 4;
    int b_nr = (lane & 7) + ((lane >> 4) << 3);
    int b_kc = (lane >> 3) & 1;

    for (int kt = 0; kt < KT; kt++) {
        int s = kt & (NSTG-1);
        CP_WAIT2();
        __syncthreads();
        int ktn = kt + NSTG - 1;
        if (ktn < KT) load_stage(ktn);
        CP_COMMIT();

        uint32_t aS = sA + s*ASZ, bS = sB + s*ASZ;
        #pragma unroll
        for (int ks = 0; ks < 2; ks++) {
            int kb = ks * 32 + a_kc * 16;
            uint32_t afr[2][4];
            #pragma unroll
            for (int mt = 0; mt < 2; mt++) {
                uint32_t ad = aS + (wm*32 + mt*16 + a_lm) * RSB + kb;
                ldsm4(afr[mt][0], afr[mt][1], afr[mt][2], afr[mt][3], ad);
            }
            uint32_t bfr[8][2];
            #pragma unroll
            for (int p = 0; p < 4; p++) {
                uint32_t r0, r1, r2, r3;
                uint32_t bd = bS + (wn*64 + p*16 + b_nr) * RSB + ks*32 + b_kc*16;
                ldsm4(r0, r1, r2, r3, bd);
                bfr[2*p][0] = r0; bfr[2*p][1] = r1;
                bfr[2*p+1][0] = r2; bfr[2*p+1][1] = r3;
            }
            #pragma unroll
            for (int mt = 0; mt < 2; mt++)
                #pragma unroll
                for (int nt = 0; nt < 8; nt++)
                    mma16816(acc[mt][nt], afr[mt], bfr[nt]);
        }
        __syncthreads();
    }

    int mbase = blockIdx.y * 128 + wm * 32;
    int nbase = blockIdx.x * 128 + wn * 64;
    int lrow = lane >> 2, lcol = (lane & 3) * 2;
    #pragma unroll
    for (int mt = 0; mt < 2; mt++) {
        #pragma unroll
        for (int nt = 0; nt < 8; nt++) {
            int row = mbase + mt*16 + lrow;
            int col = nbase + nt*8 + lcol;
            float c0 = acc[mt][nt][0], c1 = acc[mt][nt][1];
            float c2 = acc[mt][nt][2], c3 = acc[mt][nt][3];
            if (MODE == 1) {
                float b0 = bias[col], b1 = bias[col+1];
                __half2 h0 = __floats2half2_rn(fmaxf(c0+b0, 0.f), fmaxf(c1+b1, 0.f));
                __half2 h1 = __floats2half2_rn(fmaxf(c2+b0, 0.f), fmaxf(c3+b1, 0.f));
                *(__half2*)(C16 + (size_t)row * N + col)     = h0;
                *(__half2*)(C16 + (size_t)(row+8) * N + col) = h1;
            } else if (MODE == 2) {
                *(__half2*)(C16 + (size_t)row * N + col)     = __floats2half2_rn(c0, c1);
                *(__half2*)(C16 + (size_t)(row+8) * N + col) = __floats2half2_rn(c2, c3);
            } else {
                if (bias) { float b0 = bias[col], b1 = bias[col+1];
                            c0 += b0; c1 += b1; c2 += b0; c3 += b1; }
                *(float2*)(C + (size_t)row * N + col)     = make_float2(c0, c1);
                *(float2*)(C + (size_t)(row+8) * N + col) = make_float2(c2, c3);
            }
        }
    }
}

// ================= HMMA flash attention =================
// grid (NB*NH, SL/64), block 128 (4 warps x 16 query rows). Bc=64, double-buffered K/V.
#define FRS 144                        // 128B data + 16B pad per 64-half row
#define FQS (64*FRS)                   // 9216 B per tile

__global__ void __launch_bounds__(128) flashh_kernel()
{
    __shared__ __align__(16) char sm[5*FQS];   // Q | K0 K1 | V0 V1
    uint32_t s0 = smem_u32(sm);
    uint32_t sQ = s0, sK0 = s0 + FQS, sV0 = s0 + 3*FQS;
    int tid = threadIdx.x, w = tid >> 5, lane = tid & 31;
    int b = blockIdx.x >> 4, h = blockIdx.x & 15;
    int qt = blockIdx.y;

    const __half* qkv = g_qkv16;
    size_t qbase = ((size_t)(b*SL + qt*64))*DQKV + h*64;
    #pragma unroll
    for (int i = 0; i < 4; i++) {
        int idx = tid + i*128; int row = idx >> 3, ch = idx & 7;
        CP_ASYNC16(sQ + row*FRS + ch*16, qkv + qbase + (size_t)row*DQKV + ch*8);
    }
    auto loadKV = [&](int t) {
        int st = t & 1;
        size_t kbase = ((size_t)(b*SL + t*64))*DQKV + 1024 + h*64;
        #pragma unroll
        for (int i = 0; i < 4; i++) {
            int idx = tid + i*128; int row = idx >> 3, ch = idx & 7;
            CP_ASYNC16(sK0 + st*FQS + row*FRS + ch*16, qkv + kbase + (size_t)row*DQKV + ch*8);
            CP_ASYNC16(sV0 + st*FQS + row*FRS + ch*16, qkv + kbase + 1024 + (size_t)row*DQKV + ch*8);
        }
    };
    loadKV(0); CP_COMMIT();            // group: Q + KV(0)

    float m0 = -1e30f, m1 = -1e30f, l0 = 0.f, l1 = 0.f;
    float o[8][4];
    #pragma unroll
    for (int nt = 0; nt < 8; nt++)
        #pragma unroll
        for (int r = 0; r < 4; r++) o[nt][r] = 0.f;

    int a_r = lane & 15, a_k = lane >> 4;
    int b_nr = (lane & 7) + ((lane >> 4) << 3);
    int b_kc = (lane >> 3) & 1;
    int lr = lane >> 2, lc = (lane & 3) * 2;
    int r0g = b*SL + qt*64 + w*16 + lr;          // global query rows (this lane)
    uint32_t qf[4][4];

    for (int t = 0; t < SL/64; t++) {
        if (t+1 < SL/64) loadKV(t+1);
        CP_COMMIT();
        CP_WAIT1();
        __syncthreads();
        if (t == 0) {
            #pragma unroll
            for (int kc = 0; kc < 4; kc++)
                ldsm4(qf[kc][0], qf[kc][1], qf[kc][2], qf[kc][3],
                      sQ + (w*16 + a_r)*FRS + kc*32 + a_k*16);
        }
        uint32_t sK = sK0 + (t&1)*FQS, sV = sV0 + (t&1)*FQS;

        // S = Q K^T  (fp32 accum)
        float sf[8][4];
        #pragma unroll
        for (int nt = 0; nt < 8; nt++)
            #pragma unroll
            for (int r = 0; r < 4; r++) sf[nt][r] = 0.f;
        #pragma unroll
        for (int kc = 0; kc < 4; kc++) {
            uint32_t bf[8][2];
            #pragma unroll
            for (int p = 0; p < 4; p++) {
                uint32_t r0, r1, r2, r3;
                ldsm4(r0, r1, r2, r3, sK + (p*16 + b_nr)*FRS + kc*32 + b_kc*16);
                bf[2*p][0] = r0; bf[2*p][1] = r1;
                bf[2*p+1][0] = r2; bf[2*p+1][1] = r3;
            }
            #pragma unroll
            for (int nt = 0; nt < 8; nt++)
                mma16816(sf[nt], qf[kc], bf[nt]);
        }

        // scale + mask
        unsigned mw00 = g_mbits[(size_t)r0g*32 + t*2],     mw01 = g_mbits[(size_t)r0g*32 + t*2 + 1];
        unsigned mw10 = g_mbits[(size_t)(r0g+8)*32 + t*2], mw11 = g_mbits[(size_t)(r0g+8)*32 + t*2 + 1];
        #pragma unroll
        for (int nt = 0; nt < 8; nt++) {
            #pragma unroll
            for (int j = 0; j < 2; j++) {
                int c = nt*8 + lc + j;
                unsigned w0 = (c < 32) ? mw00 : mw01;
                unsigned w1 = (c < 32) ? mw10 : mw11;
                int sh = c & 31;
                float v0 = sf[nt][j]   * 0.125f;
                float v1 = sf[nt][j+2] * 0.125f;
                sf[nt][j]   = ((w0 >> sh) & 1u) ? v0 : -1e9f;
                sf[nt][j+2] = ((w1 >> sh) & 1u) ? v1 : -1e9f;
            }
        }

        // row max
        float tm0 = m0, tm1 = m1;
        #pragma unroll
        for (int nt = 0; nt < 8; nt++) {
            tm0 = fmaxf(tm0, fmaxf(sf[nt][0], sf[nt][1]));
            tm1 = fmaxf(tm1, fmaxf(sf[nt][2], sf[nt][3]));
        }
        #pragma unroll
        for (int off = 1; off <= 2; off <<= 1) {
            tm0 = fmaxf(tm0, __shfl_xor_sync(0xffffffffu, tm0, off));
            tm1 = fmaxf(tm1, __shfl_xor_sync(0xffffffffu, tm1, off));
        }
        float al0 = __expf(m0 - tm0), al1 = __expf(m1 - tm1);
        m0 = tm0; m1 = tm1;
        l0 *= al0; l1 *= al1;
        #pragma unroll
        for (int nt = 0; nt < 8; nt++) {
            o[nt][0] *= al0; o[nt][1] *= al0;
            o[nt][2] *= al1; o[nt][3] *= al1;
        }

        // p = exp(s - m), accumulate row sums, pack to A frags
        float ps0 = 0.f, ps1 = 0.f;
        uint32_t pa[4][4];
        #pragma unroll
        for (int nt = 0; nt < 8; nt++) {
            float p0 = __expf(sf[nt][0] - m0);
            float p1 = __expf(sf[nt][1] - m0);
            float p2 = __expf(sf[nt][2] - m1);
            float p3 = __expf(sf[nt][3] - m1);
            ps0 += p0 + p1; ps1 += p2 + p3;
            __half2 h01 = __floats2half2_rn(p0, p1);
            __half2 h23 = __floats2half2_rn(p2, p3);
            int cc = nt >> 1, hi = nt & 1;            // chunk, which n8 within 16
            pa[cc][2*hi]     = *(uint32_t*)&h01;      // a0 / a2
            pa[cc][2*hi + 1] = *(uint32_t*)&h23;      // a1 / a3
        }
        #pragma unroll
        for (int off = 1; off <= 2; off <<= 1) {
            ps0 += __shfl_xor_sync(0xffffffffu, ps0, off);
            ps1 += __shfl_xor_sync(0xffffffffu, ps1, off);
        }
        l0 += ps0; l1 += ps1;

        // O += P V  (V^T fragments via ldmatrix.trans)
        #pragma unroll
        for (int cc = 0; cc < 4; cc++) {            // key chunks of 16
            #pragma unroll
            for (int j = 0; j < 4; j++) {           // n chunks of 16
                uint32_t r0, r1, r2, r3;
                uint32_t vd = sV + (cc*16 + (lane&7) + ((lane>>3)&1)*8)*FRS
                            + (j*16 + ((lane>>4)<<3))*2;
                ldsm4t(r0, r1, r2, r3, vd);
                uint32_t bfr0[2] = {r0, r1}, bfr1[2] = {r2, r3};
                mma16816(o[2*j],   pa[cc], bfr0);
                mma16816(o[2*j+1], pa[cc], bfr1);
            }
        }
        __syncthreads();
    }

    float inv0 = 1.0f / l0, inv1 = 1.0f / l1;
    __half* op0 = g_ctx16 + (size_t)r0g * DM + h*64;
    __half* op1 = g_ctx16 + (size_t)(r0g + 8) * DM + h*64;
    #pragma unroll
    for (int nt = 0; nt < 8; nt++) {
        int c = nt*8 + lc;
        *(__half2*)(op0 + c) = __floats2half2_rn(o[nt][0]*inv0, o[nt][1]*inv0);
        *(__half2*)(op1 + c) = __floats2half2_rn(o[nt][2]*inv1, o[nt][3]*inv1);
    }
}

// ================= weight transpose + fp16 convert =================
__global__ __launch_bounds__(256) void transconv_kernel(const float* __restrict__ src,
                                                        __half* __restrict__ dst,
                                                        int K, int N,
                                                        size_t dO, int nInner, size_t dI)
{
    __shared__ float t[32][33];
    int z = blockIdx.z;
    src += (size_t)z * K * N;
    dst += (size_t)(z / nInner) * dO + (size_t)(z % nInner) * dI;
    int k0 = blockIdx.y * 32, n0 = blockIdx.x * 32;
    int c = threadIdx.x & 31, r0 = threadIdx.x >> 5;
    #pragma unroll
    for (int rr = 0; rr < 32; rr += 8)
        t[r0 + rr][c] = src[(size_t)(k0 + r0 + rr) * N + n0 + c];
    __syncthreads();
    #pragma unroll
    for (int rr = 0; rr < 32; rr += 8)
        dst[(size_t)(n0 + r0 + rr) * K + k0 + c] = __float2half(t[c][r0 + rr]);
}

// ================= embedding + positional encoding =================
__global__ __launch_bounds__(256) void embed_kernel(const int* __restrict__ x,
                                                    const float* __restrict__ embed)
{
    int tok = blockIdx.x;
    int l   = tok & (SL-1);
    const float* e = embed + (size_t)x[tok] * DM;
    float*  out   = g_h   + (size_t)tok * DM;
    __half* out16 = g_h16 + (size_t)tok * DM;
    const float LOG2_10000 = 13.287712379549449f;
    for (int d = threadIdx.x; d < DM; d += 256) {
        float p = (float)(d & ~1) * (1.0f / (float)DM);
        float inv_div = exp2f(-LOG2_10000 * p);
        float ang = (float)(l + 1) * inv_div;
        float pe = (d & 1) ? cosf(ang) : sinf(ang);
        float v = e[d] * 32.0f + pe;
        out[d] = v;
        out16[d] = __float2half(v);
    }
}

// ================= mask -> bitmask =================
__global__ __launch_bounds__(256) void pack_mask_kernel(const int* __restrict__ mask)
{
    size_t w = (size_t)blockIdx.x * 256 + threadIdx.x;
    if (w >= (size_t)NB*SL*SL/32) return;
    const int* p = mask + w * 32;
    unsigned bits = 0;
    #pragma unroll
    for (int j = 0; j < 32; j++) bits |= (p[j] != 0 ? 1u : 0u) << j;
    g_mbits[w] = bits;
}

// ================= residual add + layernorm =================
__global__ __launch_bounds__(256) void add_ln_kernel(const float* x, const float* y,
                                                     const float* __restrict__ sc,
                                                     const float* __restrict__ bt,
                                                     float* out, __half* out16)
{
    int tok = blockIdx.x;
    const float* xp = x + (size_t)tok * DM;
    const float* yp = y + (size_t)tok * DM;
    float*  op   = out   + (size_t)tok * DM;
    __half* op16 = out16 + (size_t)tok * DM;
    __shared__ float red[8];

    float v[4]; float sum = 0.f;
    #pragma unroll
    for (int i = 0; i < 4; i++) {
        int d = threadIdx.x + 256*i;
        v[i] = xp[d] + yp[d];
        sum += v[i];
    }
    #pragma unroll
    for (int off = 16; off > 0; off >>= 1) sum += __shfl_xor_sync(0xffffffffu, sum, off);
    if ((threadIdx.x & 31) == 0) red[threadIdx.x >> 5] = sum;
    __syncthreads();
    float tot = 0.f;
    #pragma unroll
    for (int i = 0; i < 8; i++) tot += red[i];
    float mu = tot * (1.0f / (float)DM);

    float var = 0.f;
    #pragma unroll
    for (int i = 0; i < 4; i++) { float dl = v[i] - mu; var = fmaf(dl, dl, var); }
    __syncthreads();
    #pragma unroll
    for (int off = 16; off > 0; off >>= 1) var += __shfl_xor_sync(0xffffffffu, var, off);
    if ((threadIdx.x & 31) == 0) red[threadIdx.x >> 5] = var;
    __syncthreads();
    float vtot = 0.f;
    #pragma unroll
    for (int i = 0; i < 8; i++) vtot += red[i];
    float inv = rsqrtf(vtot * (1.0f / (float)DM) + LN_EPS);

    #pragma unroll
    for (int i = 0; i < 4; i++) {
        int d = threadIdx.x + 256*i;
        float r = (v[i] - mu) * inv * sc[d] + bt[d];
        op[d] = r;
        op16[d] = __float2half(r);
    }
}

// ================= output head =================
__global__ __launch_bounds__(512) void out_kernel(const float* __restrict__ w,
                                                  const float* __restrict__ bias,
                                                  float* __restrict__ out)
{
    int b = blockIdx.x;
    const float* hp = g_h + ((size_t)(b * SL + SL - 1)) * DM;
    __shared__ float logits[NA];
    int wp = threadIdx.x >> 5, lane = threadIdx.x & 31;
    float s = 0.f;
    for (int d = lane; d < DM; d += 32) s = fmaf(hp[d], w[d * NA + wp], s);
    #pragma unroll
    for (int off = 16; off > 0; off >>= 1) s += __shfl_xor_sync(0xffffffffu, s, off);
    if (lane == 0) logits[wp] = s + bias[wp];
    __syncthreads();
    if (threadIdx.x == 0) {
        float mx = -1e30f;
        for (int a = 0; a < NA; a++) mx = fmaxf(mx, logits[a]);
        float se = 0.f;
        for (int a = 0; a < NA; a++) se += expf(logits[a] - mx);
        float lse = mx + logf(se);
        for (int a = 0; a < NA; a++) out[b * NA + a] = logits[a] - lse;
    }
}

// ================= host launch =================
template<typename T> static T* symaddr(const void* s) { void* p = nullptr; cudaGetSymbolAddress(&p, s); return (T*)p; }

extern "C" void kernel_launch(void* const* d_in, const int* in_sizes, int n_in,
                              void* d_out, int out_size)
{
    (void)in_sizes; (void)n_in; (void)out_size;
    const int*   x     = (const int*)d_in[0];
    const int*   mask  = (const int*)d_in[1];
    const float* embed = (const float*)d_in[2];
    const float* Wq    = (const float*)d_in[3];
    const float* Wk    = (const float*)d_in[4];
    const float* Wv    = (const float*)d_in[5];
    const float* Wo_w  = (const float*)d_in[6];
    const float* Wo_b  = (const float*)d_in[7];
    const float* ln1_s = (const float*)d_in[8];
    const float* ln1_b = (const float*)d_in[9];
    const float* ff_w1 = (const float*)d_in[10];
    const float* ff_b1 = (const float*)d_in[11];
    const float* ff_w2 = (const float*)d_in[12];
    const float* ff_b2 = (const float*)d_in[13];
    const float* ln2_s = (const float*)d_in[14];
    const float* ln2_b = (const float*)d_in[15];
    const float* out_w = (const float*)d_in[16];
    const float* out_b = (const float*)d_in[17];
    float* out = (float*)d_out;

    float*  h_p    = symaddr<float>(g_h);
    float*  res_p  = symaddr<float>(g_res);
    __half* qkv_p  = symaddr<__half>(g_qkv16);
    __half* h16_p  = symaddr<__half>(g_h16);
    __half* ctx16_p= symaddr<__half>(g_ctx16);
    __half* ff16_p = symaddr<__half>(g_ff16);
    __half* wqkv_p = symaddr<__half>(g_wqkv16);
    __half* wo_p   = symaddr<__half>(g_wo16);
    __half* w1_p   = symaddr<__half>(g_w116);
    __half* w2_p   = symaddr<__half>(g_w216);

    cudaFuncSetAttribute(gemm16_kernel<0>, cudaFuncAttributeMaxDynamicSharedMemorySize, GSMEM);
    cudaFuncSetAttribute(gemm16_kernel<1>, cudaFuncAttributeMaxDynamicSharedMemorySize, GSMEM);
    cudaFuncSetAttribute(gemm16_kernel<2>, cudaFuncAttributeMaxDynamicSharedMemorySize, GSMEM);

    embed_kernel<<<NT, 256>>>(x, embed);
    pack_mask_kernel<<<((size_t)NB*SL*SL/32 + 255)/256, 256>>>(mask);

    transconv_kernel<<<dim3(2, 32, NL*NH), 256>>>(Wq, wqkv_p,                   DM, DQ, (size_t)DQKV*DM, NH, (size_t)DQ*DM);
    transconv_kernel<<<dim3(2, 32, NL*NH), 256>>>(Wk, wqkv_p + (size_t)DM*DM,   DM, DQ, (size_t)DQKV*DM, NH, (size_t)DQ*DM);
    transconv_kernel<<<dim3(2, 32, NL*NH), 256>>>(Wv, wqkv_p + (size_t)2*DM*DM, DM, DQ, (size_t)DQKV*DM, NH, (size_t)DQ*DM);
    transconv_kernel<<<dim3(32, 32, NL), 256>>>(Wo_w,  wo_p, DM, DM,  (size_t)DM*DM,  1, 0);
    transconv_kernel<<<dim3(128, 32, NL), 256>>>(ff_w1, w1_p, DM, DFF, (size_t)DM*DFF, 1, 0);
    transconv_kernel<<<dim3(32, 128, NL), 256>>>(ff_w2, w2_p, DFF, DM, (size_t)DFF*DM, 1, 0);

    dim3 gQKV(DQKV/128, NT/128);
    dim3 gD(DM/128, NT/128);
    dim3 gF(DFF/128, NT/128);

    for (int i = 0; i < NL; i++) {
        gemm16_kernel<2><<<gQKV, 256, GSMEM>>>(h16_p, wqkv_p + (size_t)i*DQKV*DM, nullptr, nullptr, qkv_p, DQKV, DM);
        flashh_kernel<<<dim3(NB*NH, SL/64), 128>>>();
        gemm16_kernel<0><<<gD, 256, GSMEM>>>(ctx16_p, wo_p + (size_t)i*DM*DM, Wo_b + (size_t)i*DM, res_p, nullptr, DM, DM);
        add_ln_kernel<<<NT, 256>>>(h_p, res_p, ln1_s + (size_t)i*DM, ln1_b + (size_t)i*DM, h_p, h16_p);
        gemm16_kernel<1><<<gF, 256, GSMEM>>>(h16_p, w1_p + (size_t)i*DM*DFF, ff_b1 + (size_t)i*DFF, nullptr, ff16_p, DFF, DM);
        gemm16_kernel<0><<<gD, 256, GSMEM>>>(ff16_p, w2_p + (size_t)i*DFF*DM, ff_b2 + (size_t)i*DM, res_p, nullptr, DM, DFF);
        add_ln_kernel<<<NT, 256>>>(h_p, res_p, ln2_s + (size_t)i*DM, ln2_b + (size_t)i*DM, h_p, h16_p);
    }
    out_kernel<<<NB, 512>>>(out_w, out_b, out);
}